// round 1
// baseline (speedup 1.0000x reference)
#include <cuda_runtime.h>

#define NTOK 4096

// scratch (no cudaMalloc allowed): qkv = [b][192][4096] (q:0-63, k:64-127, v:128-191)
__device__ float g_qkv[4][192][NTOK];
__device__ float g_att[4][64][NTOK];

typedef unsigned long long u64;

// ---- packed f32x2 helpers (sm_103a FFMA2 path, PTX-only) ----
__device__ __forceinline__ u64 pk2(float lo, float hi){
  u64 r; asm("mov.b64 %0, {%1,%2};" : "=l"(r) : "f"(lo), "f"(hi)); return r;
}
__device__ __forceinline__ float2 upk2(u64 v){
  float2 f; asm("mov.b64 {%0,%1}, %2;" : "=f"(f.x), "=f"(f.y) : "l"(v)); return f;
}
__device__ __forceinline__ u64 ffma2(u64 a, u64 b, u64 c){
  u64 d; asm("fma.rn.f32x2 %0, %1, %2, %3;" : "=l"(d) : "l"(a), "l"(b), "l"(c)); return d;
}
__device__ __forceinline__ u64 fmul2(u64 a, u64 b){
  u64 d; asm("mul.rn.f32x2 %0, %1, %2;" : "=l"(d) : "l"(a), "l"(b)); return d;
}

// ---------------------------------------------------------------------------
// out[b][o][n] = bias[o] + sum_k W[o][k] * X[b][k][n]
// grid: (N/64, M/64, B), block 256.  Thread (ty,tx) owns out[4ty..+3][4tx..+3].
// ---------------------------------------------------------------------------
__global__ __launch_bounds__(256)
void gemm_bias_kernel(const float* __restrict__ W, const float* __restrict__ bias,
                      const float* __restrict__ X, float* __restrict__ out, int K)
{
  __shared__ float ws[64*65];
  __shared__ float xs[64*64];
  const int M  = gridDim.y * 64;
  const int b  = blockIdx.z;
  const int o0 = blockIdx.y * 64, n0 = blockIdx.x * 64;
  const float* Xb = X + (size_t)b * K * NTOK;
  float* Ob = out + (size_t)b * M * NTOK;
  const int tid = threadIdx.x, tx = tid & 15, ty = tid >> 4;

  u64 acc[4][2];
  #pragma unroll
  for (int i = 0; i < 4; i++){ acc[i][0] = 0ull; acc[i][1] = 0ull; }

  for (int k0 = 0; k0 < K; k0 += 64){
    __syncthreads();
    #pragma unroll
    for (int idx = tid; idx < 4096; idx += 256){
      int o = idx >> 6, k = idx & 63;
      ws[o*65 + k] = W[(size_t)(o0 + o) * K + k0 + k];
    }
    #pragma unroll
    for (int idx = tid; idx < 1024; idx += 256){
      int k = idx >> 4, f = idx & 15;
      *(float4*)(xs + k*64 + 4*f) =
          *(const float4*)(Xb + (size_t)(k0 + k) * NTOK + n0 + 4*f);
    }
    __syncthreads();
    #pragma unroll 8
    for (int k = 0; k < 64; k++){
      u64 x0 = *(const u64*)(xs + k*64 + 4*tx);
      u64 x1 = *(const u64*)(xs + k*64 + 4*tx + 2);
      #pragma unroll
      for (int i = 0; i < 4; i++){
        float w = ws[(4*ty + i)*65 + k];
        u64 wd = pk2(w, w);
        acc[i][0] = ffma2(wd, x0, acc[i][0]);
        acc[i][1] = ffma2(wd, x1, acc[i][1]);
      }
    }
  }
  #pragma unroll
  for (int i = 0; i < 4; i++){
    float bb = bias[o0 + 4*ty + i];
    float2 a0 = upk2(acc[i][0]), a1 = upk2(acc[i][1]);
    float4 r = make_float4(a0.x + bb, a0.y + bb, a1.x + bb, a1.y + bb);
    *(float4*)(Ob + (size_t)(o0 + 4*ty + i) * NTOK + n0 + 4*tx) = r;
  }
}

// ---------------------------------------------------------------------------
// Flash attention: grid (N/64, B), block 256.
// S-GEMM: thread (ty,tx) owns S[n=4ty..+3][m=4tx..+3]
// O-GEMM: thread (ty,tx) owns O[c=4tx..+3][n=4ty..+3]
// smem: qs[64][64], ks[64][64], vst[64][68] (=V^T [m][c]), ps[64][68] (=P^T [m][n])
// ---------------------------------------------------------------------------
__global__ __launch_bounds__(256)
void flash_kernel()
{
  extern __shared__ float smf[];
  float* qs  = smf;                     // 4096 floats
  float* ks  = smf + 4096;              // 4096
  float* vst = smf + 8192;              // 64*68
  float* ps  = smf + 8192 + 64*68;      // 64*68

  const int b  = blockIdx.y;
  const int n0 = blockIdx.x * 64;
  const float* gq = &g_qkv[b][0][0];
  const float* gk = &g_qkv[b][64][0];
  const float* gv = &g_qkv[b][128][0];
  const int tid = threadIdx.x, tx = tid & 15, ty = tid >> 4;

  // load Q tile, fold in the 0.125 softmax scale
  #pragma unroll
  for (int idx = tid; idx < 1024; idx += 256){
    int c = idx >> 4, f = idx & 15;
    float4 v = *(const float4*)(gq + c*NTOK + n0 + 4*f);
    v.x *= 0.125f; v.y *= 0.125f; v.z *= 0.125f; v.w *= 0.125f;
    *(float4*)(qs + c*64 + 4*f) = v;
  }

  float row_m[4], row_l[4];
  #pragma unroll
  for (int i = 0; i < 4; i++){ row_m[i] = -1e30f; row_l[i] = 0.f; }
  u64 o2[4][2];   // o2[j][ip]: (O[c=4tx+j][n=4ty+2ip], O[..][n=4ty+2ip+1])
  #pragma unroll
  for (int j = 0; j < 4; j++){ o2[j][0] = 0ull; o2[j][1] = 0ull; }

  for (int m0 = 0; m0 < NTOK; m0 += 64){
    __syncthreads();   // previous O-GEMM done before overwriting ks/vst
    #pragma unroll
    for (int idx = tid; idx < 1024; idx += 256){
      int c = idx >> 4, f = idx & 15;
      *(float4*)(ks + c*64 + 4*f) = *(const float4*)(gk + c*NTOK + m0 + 4*f);
      float4 v = *(const float4*)(gv + c*NTOK + m0 + 4*f);
      vst[(4*f + 0)*68 + c] = v.x;
      vst[(4*f + 1)*68 + c] = v.y;
      vst[(4*f + 2)*68 + c] = v.z;
      vst[(4*f + 3)*68 + c] = v.w;
    }
    __syncthreads();

    // S = (Q*scale)^T K  : s2[ip][j] packs n-pairs
    u64 s2[2][4];
    #pragma unroll
    for (int j = 0; j < 4; j++){ s2[0][j] = 0ull; s2[1][j] = 0ull; }
    #pragma unroll 8
    for (int c = 0; c < 64; c++){
      u64 q0 = *(const u64*)(qs + c*64 + 4*ty);
      u64 q1 = *(const u64*)(qs + c*64 + 4*ty + 2);
      float4 kv = *(const float4*)(ks + c*64 + 4*tx);
      u64 k0d = pk2(kv.x, kv.x), k1d = pk2(kv.y, kv.y);
      u64 k2d = pk2(kv.z, kv.z), k3d = pk2(kv.w, kv.w);
      s2[0][0] = ffma2(q0, k0d, s2[0][0]);
      s2[0][1] = ffma2(q0, k1d, s2[0][1]);
      s2[0][2] = ffma2(q0, k2d, s2[0][2]);
      s2[0][3] = ffma2(q0, k3d, s2[0][3]);
      s2[1][0] = ffma2(q1, k0d, s2[1][0]);
      s2[1][1] = ffma2(q1, k1d, s2[1][1]);
      s2[1][2] = ffma2(q1, k2d, s2[1][2]);
      s2[1][3] = ffma2(q1, k3d, s2[1][3]);
    }
    float s[4][4];
    #pragma unroll
    for (int ip = 0; ip < 2; ip++)
      #pragma unroll
      for (int j = 0; j < 4; j++){
        float2 f = upk2(s2[ip][j]);
        s[2*ip][j] = f.x; s[2*ip + 1][j] = f.y;
      }

    // online softmax over m (tile-local max -> reduce across tx -> update)
    float tm[4];
    #pragma unroll
    for (int i = 0; i < 4; i++)
      tm[i] = fmaxf(fmaxf(s[i][0], s[i][1]), fmaxf(s[i][2], s[i][3]));
    #pragma unroll
    for (int d = 1; d < 16; d <<= 1)
      #pragma unroll
      for (int i = 0; i < 4; i++)
        tm[i] = fmaxf(tm[i], __shfl_xor_sync(0xffffffffu, tm[i], d));

    float al[4], rs[4];
    #pragma unroll
    for (int i = 0; i < 4; i++){
      float nm = fmaxf(row_m[i], tm[i]);
      al[i] = __expf(row_m[i] - nm);
      row_m[i] = nm;
      rs[i] = 0.f;
    }
    #pragma unroll
    for (int i = 0; i < 4; i++)
      #pragma unroll
      for (int j = 0; j < 4; j++){
        float p = __expf(s[i][j] - row_m[i]);
        s[i][j] = p;
        rs[i] += p;
      }
    #pragma unroll
    for (int d = 1; d < 16; d <<= 1)
      #pragma unroll
      for (int i = 0; i < 4; i++)
        rs[i] += __shfl_xor_sync(0xffffffffu, rs[i], d);
    #pragma unroll
    for (int i = 0; i < 4; i++) row_l[i] = row_l[i]*al[i] + rs[i];

    u64 a2[2] = { pk2(al[0], al[1]), pk2(al[2], al[3]) };
    #pragma unroll
    for (int j = 0; j < 4; j++){
      o2[j][0] = fmul2(o2[j][0], a2[0]);
      o2[j][1] = fmul2(o2[j][1], a2[1]);
    }

    // write P^T: ps[m][n]
    #pragma unroll
    for (int j = 0; j < 4; j++)
      *(float4*)(ps + (4*tx + j)*68 + 4*ty) =
          make_float4(s[0][j], s[1][j], s[2][j], s[3][j]);
    __syncthreads();

    // O += V P : inner over m
    #pragma unroll 8
    for (int m = 0; m < 64; m++){
      u64 p0 = *(const u64*)(ps + m*68 + 4*ty);
      u64 p1 = *(const u64*)(ps + m*68 + 4*ty + 2);
      float4 vv = *(const float4*)(vst + m*68 + 4*tx);
      u64 v0 = pk2(vv.x, vv.x), v1 = pk2(vv.y, vv.y);
      u64 v2 = pk2(vv.z, vv.z), v3 = pk2(vv.w, vv.w);
      o2[0][0] = ffma2(v0, p0, o2[0][0]);  o2[0][1] = ffma2(v0, p1, o2[0][1]);
      o2[1][0] = ffma2(v1, p0, o2[1][0]);  o2[1][1] = ffma2(v1, p1, o2[1][1]);
      o2[2][0] = ffma2(v2, p0, o2[2][0]);  o2[2][1] = ffma2(v2, p1, o2[2][1]);
      o2[3][0] = ffma2(v3, p0, o2[3][0]);  o2[3][1] = ffma2(v3, p1, o2[3][1]);
    }
  }

  float inv[4];
  #pragma unroll
  for (int i = 0; i < 4; i++) inv[i] = 1.0f / row_l[i];
  u64 iv2[2] = { pk2(inv[0], inv[1]), pk2(inv[2], inv[3]) };
  #pragma unroll
  for (int j = 0; j < 4; j++){
    u64 r0 = fmul2(o2[j][0], iv2[0]);
    u64 r1 = fmul2(o2[j][1], iv2[1]);
    float2 a = upk2(r0), c = upk2(r1);
    *(float4*)(&g_att[b][4*tx + j][n0 + 4*ty]) = make_float4(a.x, a.y, c.x, c.y);
  }
}

// ---------------------------------------------------------------------------
extern "C" void kernel_launch(void* const* d_in, const int* in_sizes, int n_in,
                              void* d_out, int out_size)
{
  const float* x      = (const float*)d_in[0];
  const float* qkv_w  = (const float*)d_in[1];
  const float* qkv_b  = (const float*)d_in[2];
  const float* proj_w = (const float*)d_in[3];
  const float* proj_b = (const float*)d_in[4];
  float* out = (float*)d_out;

  void* qkv_ptr = 0; cudaGetSymbolAddress(&qkv_ptr, g_qkv);
  void* att_ptr = 0; cudaGetSymbolAddress(&att_ptr, g_att);

  const int flash_smem = (4096 + 4096 + 64*68 + 64*68) * 4;  // 67584 B
  cudaFuncSetAttribute(flash_kernel,
                       cudaFuncAttributeMaxDynamicSharedMemorySize, flash_smem);

  // QKV projection: M=192, K=256
  gemm_bias_kernel<<<dim3(64, 3, 4), 256>>>(qkv_w, qkv_b, x, (float*)qkv_ptr, 256);
  // fused attention
  flash_kernel<<<dim3(64, 4), 256, flash_smem>>>();
  // output projection: M=256, K=64
  gemm_bias_kernel<<<dim3(64, 4, 4), 256>>>(proj_w, proj_b, (const float*)att_ptr, out, 64);
}

// round 2
// speedup vs baseline: 2.5879x; 2.5879x over previous
#include <cuda_runtime.h>

#define NTOK 4096

// scratch: qkv = [b][192][4096] (q:0-63, k:64-127, v:128-191)
__device__ float g_qkv[4][192][NTOK];
__device__ float g_att[4][64][NTOK];

typedef unsigned long long u64;

// ---- packed f32x2 helpers (scalar GEMMs) ----
__device__ __forceinline__ u64 pk2(float lo, float hi){
  u64 r; asm("mov.b64 %0, {%1,%2};" : "=l"(r) : "f"(lo), "f"(hi)); return r;
}
__device__ __forceinline__ float2 upk2(u64 v){
  float2 f; asm("mov.b64 {%0,%1}, %2;" : "=f"(f.x), "=f"(f.y) : "l"(v)); return f;
}
__device__ __forceinline__ u64 ffma2(u64 a, u64 b, u64 c){
  u64 d; asm("fma.rn.f32x2 %0, %1, %2, %3;" : "=l"(d) : "l"(a), "l"(b), "l"(c)); return d;
}

// ---- tf32 helpers ----
__device__ __forceinline__ unsigned cvt_tf32(float x){
  unsigned u; asm("cvt.rna.tf32.f32 %0, %1;" : "=r"(u) : "f"(x)); return u;
}
__device__ __forceinline__ float cvt_tf32f(float x){
  return __uint_as_float(cvt_tf32(x));
}
__device__ __forceinline__ void mma_tf32(float d[4],
    unsigned a0, unsigned a1, unsigned a2, unsigned a3,
    unsigned b0, unsigned b1){
  asm("mma.sync.aligned.m16n8k8.row.col.f32.tf32.tf32.f32 "
      "{%0,%1,%2,%3}, {%4,%5,%6,%7}, {%8,%9}, {%0,%1,%2,%3};"
      : "+f"(d[0]), "+f"(d[1]), "+f"(d[2]), "+f"(d[3])
      : "r"(a0), "r"(a1), "r"(a2), "r"(a3), "r"(b0), "r"(b1));
}

// ---------------------------------------------------------------------------
// out[b][o][n] = bias[o] + sum_k W[o][k] * X[b][k][n]   (scalar fp32, FFMA2)
// ---------------------------------------------------------------------------
__global__ __launch_bounds__(256)
void gemm_bias_kernel(const float* __restrict__ W, const float* __restrict__ bias,
                      const float* __restrict__ X, float* __restrict__ out, int K)
{
  __shared__ float ws[64*65];
  __shared__ float xs[64*64];
  const int M  = gridDim.y * 64;
  const int b  = blockIdx.z;
  const int o0 = blockIdx.y * 64, n0 = blockIdx.x * 64;
  const float* Xb = X + (size_t)b * K * NTOK;
  float* Ob = out + (size_t)b * M * NTOK;
  const int tid = threadIdx.x, tx = tid & 15, ty = tid >> 4;

  u64 acc[4][2];
  #pragma unroll
  for (int i = 0; i < 4; i++){ acc[i][0] = 0ull; acc[i][1] = 0ull; }

  for (int k0 = 0; k0 < K; k0 += 64){
    __syncthreads();
    #pragma unroll
    for (int idx = tid; idx < 4096; idx += 256){
      int o = idx >> 6, k = idx & 63;
      ws[o*65 + k] = W[(size_t)(o0 + o) * K + k0 + k];
    }
    #pragma unroll
    for (int idx = tid; idx < 1024; idx += 256){
      int k = idx >> 4, f = idx & 15;
      *(float4*)(xs + k*64 + 4*f) =
          *(const float4*)(Xb + (size_t)(k0 + k) * NTOK + n0 + 4*f);
    }
    __syncthreads();
    #pragma unroll 8
    for (int k = 0; k < 64; k++){
      u64 x0 = *(const u64*)(xs + k*64 + 4*tx);
      u64 x1 = *(const u64*)(xs + k*64 + 4*tx + 2);
      #pragma unroll
      for (int i = 0; i < 4; i++){
        float w = ws[(4*ty + i)*65 + k];
        u64 wd = pk2(w, w);
        acc[i][0] = ffma2(wd, x0, acc[i][0]);
        acc[i][1] = ffma2(wd, x1, acc[i][1]);
      }
    }
  }
  #pragma unroll
  for (int i = 0; i < 4; i++){
    float bb = bias[o0 + 4*ty + i];
    float2 a0 = upk2(acc[i][0]), a1 = upk2(acc[i][1]);
    float4 r = make_float4(a0.x + bb, a0.y + bb, a1.x + bb, a1.y + bb);
    *(float4*)(Ob + (size_t)(o0 + 4*ty + i) * NTOK + n0 + 4*tx) = r;
  }
}

// ---------------------------------------------------------------------------
// tf32 flash attention.
// grid (NTOK/128, B), 256 threads (8 warps). Warp w owns query rows
// [16w, 16w+16) of the 128-row block tile. KV tiles of 64.
// smem: qs[n][c] stride 68 (pre-scaled, tf32-rounded)
//       ks[c][m] stride 72
//       vs[c][m] stride 76   (B-frag reads V[m][c] = vs[c][m])
// All hot fragment LDS patterns are bank-conflict-free for these strides.
// ---------------------------------------------------------------------------
#define QS_STR 68
#define KS_STR 72
#define VS_STR 76

__global__ __launch_bounds__(256)
void flash_tf32_kernel()
{
  extern __shared__ float smf[];
  float* qs = smf;                      // 128*68 = 8704 floats
  float* ks = smf + 128*QS_STR;         // 64*72  = 4608
  float* vs = ks + 64*KS_STR;           // 64*76  = 4864

  const int b  = blockIdx.y;
  const int n0 = blockIdx.x * 128;
  const float* gq = &g_qkv[b][0][0];
  const float* gk = &g_qkv[b][64][0];
  const float* gv = &g_qkv[b][128][0];

  const int tid  = threadIdx.x;
  const int warp = tid >> 5, lane = tid & 31;
  const int g = lane >> 2, t = lane & 3;

  // Q fill: transpose [c][n] -> qs[n][c], fold 0.125 scale, round to tf32
  #pragma unroll
  for (int i = tid; i < 2048; i += 256){
    int c = i >> 5, f = i & 31;           // 32 float4 chunks of n per c-row
    float4 v = *(const float4*)(gq + c*NTOK + n0 + 4*f);
    qs[(4*f+0)*QS_STR + c] = cvt_tf32f(v.x * 0.125f);
    qs[(4*f+1)*QS_STR + c] = cvt_tf32f(v.y * 0.125f);
    qs[(4*f+2)*QS_STR + c] = cvt_tf32f(v.z * 0.125f);
    qs[(4*f+3)*QS_STR + c] = cvt_tf32f(v.w * 0.125f);
  }

  float row_m0 = -1e30f, row_m1 = -1e30f;
  float row_l0 = 0.f,    row_l1 = 0.f;
  float oacc[8][4];
  #pragma unroll
  for (int cf = 0; cf < 8; cf++)
    #pragma unroll
    for (int j = 0; j < 4; j++) oacc[cf][j] = 0.f;

  const int arow0 = (16*warp + g) * QS_STR;
  const int arow1 = (16*warp + g + 8) * QS_STR;

  for (int m0 = 0; m0 < NTOK; m0 += 64){
    __syncthreads();   // previous PV reads of ks/vs complete
    // K/V fill (row copy, tf32-rounded)
    #pragma unroll
    for (int i = tid; i < 1024; i += 256){
      int c = i >> 4, f = i & 15;
      float4 kv = *(const float4*)(gk + c*NTOK + m0 + 4*f);
      float* kp = ks + c*KS_STR + 4*f;
      kp[0] = cvt_tf32f(kv.x); kp[1] = cvt_tf32f(kv.y);
      kp[2] = cvt_tf32f(kv.z); kp[3] = cvt_tf32f(kv.w);
      float4 vv = *(const float4*)(gv + c*NTOK + m0 + 4*f);
      float* vp = vs + c*VS_STR + 4*f;
      vp[0] = cvt_tf32f(vv.x); vp[1] = cvt_tf32f(vv.y);
      vp[2] = cvt_tf32f(vv.z); vp[3] = cvt_tf32f(vv.w);
    }
    __syncthreads();

    // ---- S = Q^T K : 8 m-frags x 8 k-steps ----
    float sacc[8][4];
    #pragma unroll
    for (int mf = 0; mf < 8; mf++)
      #pragma unroll
      for (int j = 0; j < 4; j++) sacc[mf][j] = 0.f;

    #pragma unroll
    for (int kk = 0; kk < 8; kk++){
      unsigned a0 = __float_as_uint(qs[arow0 + 8*kk + t]);
      unsigned a1 = __float_as_uint(qs[arow1 + 8*kk + t]);
      unsigned a2 = __float_as_uint(qs[arow0 + 8*kk + t + 4]);
      unsigned a3 = __float_as_uint(qs[arow1 + 8*kk + t + 4]);
      #pragma unroll
      for (int mf = 0; mf < 8; mf++){
        unsigned b0 = __float_as_uint(ks[(8*kk + t    )*KS_STR + 8*mf + g]);
        unsigned b1 = __float_as_uint(ks[(8*kk + t + 4)*KS_STR + 8*mf + g]);
        mma_tf32(sacc[mf], a0, a1, a2, a3, b0, b1);
      }
    }

    // ---- online softmax over m (rows g / g+8 of this warp's tile) ----
    float tm0 = -1e30f, tm1 = -1e30f;
    #pragma unroll
    for (int mf = 0; mf < 8; mf++){
      tm0 = fmaxf(tm0, fmaxf(sacc[mf][0], sacc[mf][1]));
      tm1 = fmaxf(tm1, fmaxf(sacc[mf][2], sacc[mf][3]));
    }
    tm0 = fmaxf(tm0, __shfl_xor_sync(0xffffffffu, tm0, 1));
    tm0 = fmaxf(tm0, __shfl_xor_sync(0xffffffffu, tm0, 2));
    tm1 = fmaxf(tm1, __shfl_xor_sync(0xffffffffu, tm1, 1));
    tm1 = fmaxf(tm1, __shfl_xor_sync(0xffffffffu, tm1, 2));

    float nm0 = fmaxf(row_m0, tm0), nm1 = fmaxf(row_m1, tm1);
    float al0 = __expf(row_m0 - nm0), al1 = __expf(row_m1 - nm1);
    row_m0 = nm0; row_m1 = nm1;

    float rs0 = 0.f, rs1 = 0.f;
    unsigned pa[8][4];
    #pragma unroll
    for (int mf = 0; mf < 8; mf++){
      float p0 = __expf(sacc[mf][0] - nm0); rs0 += p0; pa[mf][0] = cvt_tf32(p0);
      float p1 = __expf(sacc[mf][1] - nm0); rs0 += p1; pa[mf][1] = cvt_tf32(p1);
      float p2 = __expf(sacc[mf][2] - nm1); rs1 += p2; pa[mf][2] = cvt_tf32(p2);
      float p3 = __expf(sacc[mf][3] - nm1); rs1 += p3; pa[mf][3] = cvt_tf32(p3);
    }
    rs0 += __shfl_xor_sync(0xffffffffu, rs0, 1);
    rs0 += __shfl_xor_sync(0xffffffffu, rs0, 2);
    rs1 += __shfl_xor_sync(0xffffffffu, rs1, 1);
    rs1 += __shfl_xor_sync(0xffffffffu, rs1, 2);
    row_l0 = row_l0 * al0 + rs0;
    row_l1 = row_l1 * al1 + rs1;

    #pragma unroll
    for (int cf = 0; cf < 8; cf++){
      oacc[cf][0] *= al0; oacc[cf][1] *= al0;
      oacc[cf][2] *= al1; oacc[cf][3] *= al1;
    }

    // ---- O += P V : P A-frags come from sacc fragments via shuffle ----
    const int lA = (g << 2) + (t >> 1);
    const int lB = lA + 2;
    const bool odd = (t & 1);
    #pragma unroll
    for (int kk = 0; kk < 8; kk++){
      unsigned x0 = __shfl_sync(0xffffffffu, pa[kk][0], lA);
      unsigned x1 = __shfl_sync(0xffffffffu, pa[kk][1], lA);
      unsigned x2 = __shfl_sync(0xffffffffu, pa[kk][2], lA);
      unsigned x3 = __shfl_sync(0xffffffffu, pa[kk][3], lA);
      unsigned y0 = __shfl_sync(0xffffffffu, pa[kk][0], lB);
      unsigned y1 = __shfl_sync(0xffffffffu, pa[kk][1], lB);
      unsigned y2 = __shfl_sync(0xffffffffu, pa[kk][2], lB);
      unsigned y3 = __shfl_sync(0xffffffffu, pa[kk][3], lB);
      unsigned a0 = odd ? x1 : x0;
      unsigned a1 = odd ? x3 : x2;
      unsigned a2 = odd ? y1 : y0;
      unsigned a3 = odd ? y3 : y2;
      #pragma unroll
      for (int cf = 0; cf < 8; cf++){
        unsigned b0 = __float_as_uint(vs[(8*cf + g)*VS_STR + 8*kk + t]);
        unsigned b1 = __float_as_uint(vs[(8*cf + g)*VS_STR + 8*kk + t + 4]);
        mma_tf32(oacc[cf], a0, a1, a2, a3, b0, b1);
      }
    }
  }

  // ---- epilogue: scale by 1/l, write g_att[b][c][n] ----
  float inv0 = 1.f / row_l0, inv1 = 1.f / row_l1;
  int ng = n0 + 16*warp + g;
  #pragma unroll
  for (int cf = 0; cf < 8; cf++){
    int c0 = 8*cf + 2*t;
    g_att[b][c0    ][ng    ] = oacc[cf][0] * inv0;
    g_att[b][c0 + 1][ng    ] = oacc[cf][1] * inv0;
    g_att[b][c0    ][ng + 8] = oacc[cf][2] * inv1;
    g_att[b][c0 + 1][ng + 8] = oacc[cf][3] * inv1;
  }
}

// ---------------------------------------------------------------------------
extern "C" void kernel_launch(void* const* d_in, const int* in_sizes, int n_in,
                              void* d_out, int out_size)
{
  const float* x      = (const float*)d_in[0];
  const float* qkv_w  = (const float*)d_in[1];
  const float* qkv_b  = (const float*)d_in[2];
  const float* proj_w = (const float*)d_in[3];
  const float* proj_b = (const float*)d_in[4];
  float* out = (float*)d_out;

  void* qkv_ptr = 0; cudaGetSymbolAddress(&qkv_ptr, g_qkv);
  void* att_ptr = 0; cudaGetSymbolAddress(&att_ptr, g_att);

  const int flash_smem = (128*QS_STR + 64*KS_STR + 64*VS_STR) * 4;  // 72704 B
  cudaFuncSetAttribute(flash_tf32_kernel,
                       cudaFuncAttributeMaxDynamicSharedMemorySize, flash_smem);

  // QKV projection: M=192, K=256
  gemm_bias_kernel<<<dim3(64, 3, 4), 256>>>(qkv_w, qkv_b, x, (float*)qkv_ptr, 256);
  // fused tf32 attention
  flash_tf32_kernel<<<dim3(NTOK/128, 4), 256, flash_smem>>>();
  // output projection: M=256, K=64
  gemm_bias_kernel<<<dim3(64, 4, 4), 256>>>(proj_w, proj_b, (const float*)att_ptr, out, 64);
}